// round 16
// baseline (speedup 1.0000x reference)
#include <cuda_runtime.h>
#include <cstdint>

#define BB 2
#define PP 200000
#define QQ 100
#define TILE 128                      // rows per CTA tile
#define TILE_BYTES (TILE * QQ * 4)    // 51200
#define CROWS 32                      // rows per chunk
#define CBYTES (CROWS * QQ * 4)       // 12800
#define FULLM 0xffffffffu

// Per-batch nonempty bitmask (zero at load; remap self-cleans every replay).
__device__ unsigned g_bits[BB][4];
__device__ unsigned g_tick;

__device__ __forceinline__ float fast_rcp(float d) {
    float r;
    asm("rcp.approx.f32 %0, %1;" : "=f"(r) : "f"(d));
    r = fmaf(fmaf(-d, r, 1.0f), r, r);
    return r;
}

// 16B-granule swizzle; bits [6:4] ^= bits [9:7]. Bits 0-3 untouched, so it is
// valid for any byte offset whose 16B-chunk was stored swizzled.
__device__ __forceinline__ unsigned swz(unsigned byteoff) {
    return byteoff ^ ((byteoff >> 3) & 0x70u);
}

// ---------------------------------------------------------------------------
// Main kernel — intra-CTA 4-chunk cp.async pipeline, 4 threads per row.
// Issue: 4 chunks as 4 commit groups (threads 0-99 issue 8x16B per chunk).
// Table: ordered ballot compaction of kept queries (validated since R6).
// Chunk c: wait_group(3-c) + barrier, then thread t computes row c*32+(t>>2),
//   entries j = (t&3)+4i over the compacted list; 2-round shfl_xor merges
//   (M, pos, S) within each 4-lane row group (min-pos tiebreak == first max).
// Leaders (t&3==0) write sem/ins-tmp/conf and set smem flags.
// ---------------------------------------------------------------------------
__global__ void __launch_bounds__(TILE) main_kernel(
    const float* __restrict__ logits,
    const float* __restrict__ masks,
    const unsigned char* __restrict__ pad,
    float* __restrict__ out)
{
    extern __shared__ float s_x[];                 // TILE*QQ floats, swizzled
    __shared__ __align__(16) int   kidx[112];
    __shared__ __align__(16) float ks[112];
    __shared__ int s_cnt[4];
    __shared__ int flags[QQ];

    const int t = threadIdx.x;
    const int wid = t >> 5, lane = t & 31;
    const int b = blockIdx.y;
    const int tile0 = blockIdx.x * TILE;
    const size_t gbase = (size_t)b * PP;

    // --- Issue all 4 chunks as separate groups (loads first) --------------
    {
        const char* gsrc = reinterpret_cast<const char*>(masks)
                         + (gbase + (size_t)tile0) * (QQ * 4);
        unsigned sbase = (unsigned)__cvta_generic_to_shared(s_x);
        size_t avail = ((size_t)PP - tile0) * (QQ * 4);
        #pragma unroll
        for (int c = 0; c < 4; c++) {
            if (t < 100) {
                #pragma unroll
                for (int i = 0; i < 8; i++) {
                    unsigned off = (unsigned)c * CBYTES + (unsigned)(i * 100 + t) * 16u;
                    size_t go = (off < avail) ? (size_t)off : (avail - 16);
                    asm volatile("cp.async.cg.shared.global [%0], [%1], 16;"
                                 :: "r"(sbase + swz(off)), "l"(gsrc + go));
                }
            }
            asm volatile("cp.async.commit_group;");   // all threads: counts agree
        }
    }

    // --- Keep/score table: ordered compaction (overlaps chunk arrivals) ---
    if (t < QQ) flags[t] = 0;
    bool kp = false; float sv = 0.0f;
    if (t < QQ) {
        float l0 = logits[(b * QQ + t) * 2 + 0];
        float l1 = logits[(b * QQ + t) * 2 + 1];
        sv = fmaxf(l0, l1);
        kp = !(l1 > l0);                 // argmax first-tie -> label 0 (kept)
    }
    unsigned bal = __ballot_sync(FULLM, kp);
    if (lane == 0) s_cnt[wid] = __popc(bal);
    __syncthreads();
    int woff = 0;
    #pragma unroll
    for (int w = 0; w < 4; w++) if (w < wid) woff += s_cnt[w];
    const int nk  = s_cnt[0] + s_cnt[1] + s_cnt[2] + s_cnt[3];
    const int nk4 = (nk + 3) & ~3;
    if (kp) {
        int pos = woff + __popc(bal & ((1u << lane) - 1u));
        kidx[pos] = t; ks[pos] = sv;
    }
    if (t < nk4 - nk) {                  // pad: huge-negative v, exp -> 0
        kidx[nk + t] = 0; ks[nk + t] = -1e30f;
    }
    __syncthreads();                     // table ready for all

    const char* srow = reinterpret_cast<const char*>(s_x);
    const int q = t & 3;                 // quarter within row
    const int rloc = t >> 2;             // local row 0..31

    // --- Per-chunk pipeline ------------------------------------------------
    #define CHUNK_BODY(CC, WN)                                                 \
    {                                                                          \
        asm volatile("cp.async.wait_group " #WN ";" ::: "memory");             \
        __syncthreads();                                                       \
        const int R = (CC) * CROWS + rloc;                                     \
        const int row = tile0 + R;                                             \
        const unsigned rowb = (unsigned)R * (QQ * 4);                          \
        float M = -3.4e38f; int pos = 0; float S = 0.0f;                       \
        for (int j = q; j < nk4; j += 4) {                                     \
            int   ci = kidx[j];                                                \
            float sc = ks[j];                                                  \
            float x = *reinterpret_cast<const float*>(srow + swz(rowb + 4u * ci)); \
            float e = __expf(-fabsf(x));                                       \
            float num = (x < 0.0f) ? e : 1.0f;                                 \
            float sig = num * fast_rcp(1.0f + e);                              \
            float v = sc * sig;                                                \
            S += __expf(v);                                                    \
            if (v > M) { M = v; pos = j; }                                     \
        }                                                                      \
        /* merge 4 lanes of the row: max with min-pos tiebreak, and sum */     \
        {                                                                      \
            float Mo = __shfl_xor_sync(FULLM, M, 1);                           \
            int   po = __shfl_xor_sync(FULLM, pos, 1);                         \
            float So = __shfl_xor_sync(FULLM, S, 1);                           \
            S += So;                                                           \
            if (Mo > M || (Mo == M && po < pos)) { M = Mo; pos = po; }         \
            Mo = __shfl_xor_sync(FULLM, M, 2);                                 \
            po = __shfl_xor_sync(FULLM, pos, 2);                               \
            So = __shfl_xor_sync(FULLM, S, 2);                                 \
            S += So;                                                           \
            if (Mo > M || (Mo == M && po < pos)) { M = Mo; pos = po; }         \
        }                                                                      \
        if (q == 0 && row < PP) {                                              \
            int   mid  = kidx[pos];                                            \
            float smid = ks[pos];                                              \
            float sig_mid = M * fast_rcp(smid);                                \
            bool validp = (nk > 0) && (sig_mid >= 1e-3f) &&                    \
                          (pad[gbase + row] == 0);                             \
            size_t base = gbase + row;                                         \
            out[base] = 0.0f;                                       /* sem */  \
            out[(size_t)BB * PP + base] = validp ? (float)(mid + 1) : 0.0f;    \
            out[(size_t)2 * BB * PP + base] = __expf(M) * fast_rcp(S);         \
            if (validp) flags[mid] = 1;                                        \
        }                                                                      \
    }

    CHUNK_BODY(0, 3)
    CHUNK_BODY(1, 2)
    CHUNK_BODY(2, 1)
    CHUNK_BODY(3, 0)
    #undef CHUNK_BODY

    __syncthreads();
    // --- Epilogue: flags -> 4 ballot words -> 4 no-return atomics ---------
    {
        bool fp = (t < QQ) ? (flags[t] != 0) : false;
        unsigned word = __ballot_sync(FULLM, fp);
        if (lane == 0 && word) atomicOr(&g_bits[b][wid], word);
    }
}

// ---------------------------------------------------------------------------
// Remap kernel: seg_id(q) = prefix-popcount of g_bits, then SELF-CLEAN via
// ticket taken after the read (last block zeroes g_bits/g_tick for replay).
// ---------------------------------------------------------------------------
__global__ void __launch_bounds__(256) remap_kernel(float* __restrict__ out) {
    __shared__ unsigned sw[BB][4];
    __shared__ int      sp[BB][4];     // exclusive word-prefix popcounts
    const int t = threadIdx.x;
    const int i = blockIdx.x * 256 + t;                // one float4 per thread
    const int i0 = i * 4;
    const bool act = (i0 < BB * PP);
    float4* p4 = reinterpret_cast<float4*>(out + (size_t)BB * PP) + i;
    float4 v = make_float4(0.f, 0.f, 0.f, 0.f);
    if (act) v = *p4;                                  // in flight during setup

    if (t < BB * 4) sw[t >> 2][t & 3] = g_bits[t >> 2][t & 3];
    __syncthreads();                     // all reads of g_bits complete
    if (t == 0) {
        unsigned tk = atomicAdd(&g_tick, 1u);
        if (tk == gridDim.x - 1) {
            __threadfence();
            #pragma unroll
            for (int w = 0; w < 4; w++) { g_bits[0][w] = 0; g_bits[1][w] = 0; }
            g_tick = 0;
        }
    }
    if (t < BB) {
        int run = 0;
        #pragma unroll
        for (int w = 0; w < 4; w++) { sp[t][w] = run; run += __popc(sw[t][w]); }
    }
    __syncthreads();

    if (act) {
        const int b = (i0 >= PP) ? 1 : 0;              // PP % 4 == 0
        float r[4] = {v.x, v.y, v.z, v.w};
        #pragma unroll
        for (int e = 0; e < 4; e++) {
            if (r[e] != 0.0f) {
                int qq = (int)r[e] - 1;                // winning query index
                int w = qq >> 5;
                unsigned m = sw[b][w] & (0xffffffffu >> (31 - (qq & 31)));
                r[e] = (float)(sp[b][w] + __popc(m));  // inclusive prefix
            }
        }
        *p4 = make_float4(r[0], r[1], r[2], r[3]);
    }
}

extern "C" void kernel_launch(void* const* d_in, const int* in_sizes, int n_in,
                              void* d_out, int out_size) {
    const float* logits = (const float*)d_in[0];
    const float* masks  = (const float*)d_in[1];
    const unsigned char* pad = (const unsigned char*)d_in[2];
    float* out = (float*)d_out;

    static bool attr_set = false;
    if (!attr_set) {
        cudaFuncSetAttribute(main_kernel,
                             cudaFuncAttributeMaxDynamicSharedMemorySize,
                             TILE_BYTES);
        attr_set = true;
    }

    dim3 grid((PP + TILE - 1) / TILE, BB);
    main_kernel<<<grid, TILE, TILE_BYTES>>>(logits, masks, pad, out);

    remap_kernel<<<(BB * PP / 4 + 255) / 256, 256>>>(out);
}

// round 17
// speedup vs baseline: 1.3882x; 1.3882x over previous
#include <cuda_runtime.h>
#include <cstdint>

#define BB 2
#define PP 200000
#define QQ 100
#define TILE 64                        // rows per CTA (halved: 8 CTAs/SM)
#define NTHR 128                       // threads per CTA (64 compute rows)
#define TILE_BYTES (TILE * QQ * 4)     // 25600
#define FULLM 0xffffffffu

// Per-batch nonempty bitmask (zero at load; remap self-cleans every replay).
__device__ unsigned g_bits[BB][4];
__device__ unsigned g_tick;

__device__ __forceinline__ float fast_rcp(float d) {
    float r;
    asm("rcp.approx.f32 %0, %1;" : "=f"(r) : "f"(d));
    r = fmaf(fmaf(-d, r, 1.0f), r, r);
    return r;
}

// 16B-granule swizzle, applied identically at cp.async dst and gathered LDS.
__device__ __forceinline__ unsigned swz(unsigned byteoff) {
    return byteoff ^ ((byteoff >> 3) & 0x70u);
}

// ---------------------------------------------------------------------------
// Main kernel — R8 one-shot shape, half-size tile for 8 CTAs/SM.
// A: cp.async.cg whole 25.6KB tile (issued first, one group).
// B: keep/score + ordered ballot compaction (identical to validated rounds).
// C: single wait + barrier; threads 0-63 each compute one row with the exact
//    validated numerics; threads 64-127 idle through compute.
// Epilogue: flags -> ballot words -> atomicOr.
// ---------------------------------------------------------------------------
__global__ void __launch_bounds__(NTHR) main_kernel(
    const float* __restrict__ logits,
    const float* __restrict__ masks,
    const unsigned char* __restrict__ pad,
    float* __restrict__ out)
{
    extern __shared__ float s_x[];                 // TILE*QQ floats, swizzled
    __shared__ __align__(16) int   kidx[112];
    __shared__ __align__(16) float ks[112];
    __shared__ int s_cnt[4];
    __shared__ int flags[QQ];

    const int t = threadIdx.x;
    const int wid = t >> 5, lane = t & 31;
    const int b = blockIdx.y;
    const int tile0 = blockIdx.x * TILE;
    const size_t gbase = (size_t)b * PP;

    // --- Phase A: issue loads FIRST (1600 16B chunks / 128 threads) -------
    {
        const char* gsrc = reinterpret_cast<const char*>(masks)
                         + (gbase + (size_t)tile0) * (QQ * 4);
        unsigned sbase = (unsigned)__cvta_generic_to_shared(s_x);
        size_t avail = ((size_t)PP - tile0) * (QQ * 4);
        #pragma unroll
        for (int k = 0; k < 13; k++) {
            unsigned off = (unsigned)(k * NTHR + t) * 16u;    // up to 26608
            if (off < TILE_BYTES) {
                size_t go = (off < avail) ? (size_t)off : (avail - 16);
                asm volatile("cp.async.cg.shared.global [%0], [%1], 16;"
                             :: "r"(sbase + swz(off)), "l"(gsrc + go));
            }
        }
        asm volatile("cp.async.commit_group;");
    }

    // --- Phase B: keep + ordered compaction (overlaps with loads) ---------
    if (t < QQ) flags[t] = 0;
    bool kp = false; float sv = 0.0f;
    if (t < QQ) {
        float l0 = logits[(b * QQ + t) * 2 + 0];
        float l1 = logits[(b * QQ + t) * 2 + 1];
        sv = fmaxf(l0, l1);
        kp = !(l1 > l0);                 // argmax first-tie -> label 0 (kept)
    }
    unsigned bal = __ballot_sync(FULLM, kp);
    if (lane == 0) s_cnt[wid] = __popc(bal);
    __syncthreads();
    int woff = 0;
    #pragma unroll
    for (int w = 0; w < 4; w++) if (w < wid) woff += s_cnt[w];
    const int nk  = s_cnt[0] + s_cnt[1] + s_cnt[2] + s_cnt[3];
    const int nk4 = (nk + 3) & ~3;
    if (kp) {
        int pos = woff + __popc(bal & ((1u << lane) - 1u));
        kidx[pos] = t; ks[pos] = sv;
    }
    if (t < nk4 - nk) {                  // pad: huge-negative v, exp -> 0
        kidx[nk + t] = 0; ks[nk + t] = -1e30f;
    }

    asm volatile("cp.async.wait_group 0;" ::: "memory");
    __syncthreads();

    // --- Phase C: compute (threads 0..63, one row each) --------------------
    if (t < TILE) {
        const int p = tile0 + t;
        const bool active = (p < PP);
        const int pc = active ? p : (PP - 1);
        const char* srow = reinterpret_cast<const char*>(s_x);
        const unsigned rowb = (unsigned)t * (QQ * 4);

        float M = -3.4e38f; int jm = 0;
        float S0 = 0.0f, S1 = 0.0f, S2 = 0.0f, S3 = 0.0f;
        const int4*   k4 = reinterpret_cast<const int4*>(kidx);
        const float4* s4 = reinterpret_cast<const float4*>(ks);

        for (int j4 = 0; j4 < (nk4 >> 2); j4++) {
            int4   ki = k4[j4];                        // broadcast LDS.128
            float4 ss = s4[j4];
            {   float x = *reinterpret_cast<const float*>(srow + swz(rowb + 4u * ki.x));
                float e = __expf(-fabsf(x));
                float num = (x < 0.0f) ? e : 1.0f;
                float sig = num * fast_rcp(1.0f + e);
                float v = ss.x * sig;
                S0 += __expf(v);
                if (v > M) { M = v; jm = 4 * j4 + 0; } }
            {   float x = *reinterpret_cast<const float*>(srow + swz(rowb + 4u * ki.y));
                float e = __expf(-fabsf(x));
                float num = (x < 0.0f) ? e : 1.0f;
                float sig = num * fast_rcp(1.0f + e);
                float v = ss.y * sig;
                S1 += __expf(v);
                if (v > M) { M = v; jm = 4 * j4 + 1; } }
            {   float x = *reinterpret_cast<const float*>(srow + swz(rowb + 4u * ki.z));
                float e = __expf(-fabsf(x));
                float num = (x < 0.0f) ? e : 1.0f;
                float sig = num * fast_rcp(1.0f + e);
                float v = ss.z * sig;
                S2 += __expf(v);
                if (v > M) { M = v; jm = 4 * j4 + 2; } }
            {   float x = *reinterpret_cast<const float*>(srow + swz(rowb + 4u * ki.w));
                float e = __expf(-fabsf(x));
                float num = (x < 0.0f) ? e : 1.0f;
                float sig = num * fast_rcp(1.0f + e);
                float v = ss.w * sig;
                S3 += __expf(v);
                if (v > M) { M = v; jm = 4 * j4 + 3; } }
        }
        float S = (S0 + S1) + (S2 + S3);

        int   mid  = kidx[jm];
        float smid = ks[jm];
        float sig_mid = M * fast_rcp(smid);
        bool validp = active && (nk > 0) && (sig_mid >= 1e-3f) &&
                      (pad[gbase + pc] == 0);

        if (validp) flags[mid] = 1;      // benign race: same value

        if (active) {
            size_t base = gbase + p;
            out[base] = 0.0f;                                               // sem
            out[(size_t)BB * PP + base] = validp ? (float)(mid + 1) : 0.0f; // tmp
            out[(size_t)2 * BB * PP + base] = __expf(M) * fast_rcp(S);      // conf
        }
    }

    __syncthreads();
    // --- Epilogue: flags -> 4 ballot words -> 4 no-return atomics ---------
    {
        bool fp = (t < QQ) ? (flags[t] != 0) : false;
        unsigned word = __ballot_sync(FULLM, fp);
        if (lane == 0 && word) atomicOr(&g_bits[b][wid], word);
    }
}

// ---------------------------------------------------------------------------
// Remap kernel: seg_id(q) = prefix-popcount of g_bits, then SELF-CLEAN via
// ticket taken after the read (last block zeroes g_bits/g_tick for replay).
// ---------------------------------------------------------------------------
__global__ void __launch_bounds__(256) remap_kernel(float* __restrict__ out) {
    __shared__ unsigned sw[BB][4];
    __shared__ int      sp[BB][4];     // exclusive word-prefix popcounts
    const int t = threadIdx.x;
    const int i = blockIdx.x * 256 + t;                // one float4 per thread
    const int i0 = i * 4;
    const bool act = (i0 < BB * PP);
    float4* p4 = reinterpret_cast<float4*>(out + (size_t)BB * PP) + i;
    float4 v = make_float4(0.f, 0.f, 0.f, 0.f);
    if (act) v = *p4;                                  // in flight during setup

    if (t < BB * 4) sw[t >> 2][t & 3] = g_bits[t >> 2][t & 3];
    __syncthreads();                     // all reads of g_bits complete
    if (t == 0) {
        unsigned tk = atomicAdd(&g_tick, 1u);
        if (tk == gridDim.x - 1) {
            __threadfence();
            #pragma unroll
            for (int w = 0; w < 4; w++) { g_bits[0][w] = 0; g_bits[1][w] = 0; }
            g_tick = 0;
        }
    }
    if (t < BB) {
        int run = 0;
        #pragma unroll
        for (int w = 0; w < 4; w++) { sp[t][w] = run; run += __popc(sw[t][w]); }
    }
    __syncthreads();

    if (act) {
        const int b = (i0 >= PP) ? 1 : 0;              // PP % 4 == 0
        float r[4] = {v.x, v.y, v.z, v.w};
        #pragma unroll
        for (int e = 0; e < 4; e++) {
            if (r[e] != 0.0f) {
                int qq = (int)r[e] - 1;                // winning query index
                int w = qq >> 5;
                unsigned m = sw[b][w] & (0xffffffffu >> (31 - (qq & 31)));
                r[e] = (float)(sp[b][w] + __popc(m));  // inclusive prefix
            }
        }
        *p4 = make_float4(r[0], r[1], r[2], r[3]);
    }
}

extern "C" void kernel_launch(void* const* d_in, const int* in_sizes, int n_in,
                              void* d_out, int out_size) {
    const float* logits = (const float*)d_in[0];
    const float* masks  = (const float*)d_in[1];
    const unsigned char* pad = (const unsigned char*)d_in[2];
    float* out = (float*)d_out;

    static bool attr_set = false;
    if (!attr_set) {
        cudaFuncSetAttribute(main_kernel,
                             cudaFuncAttributeMaxDynamicSharedMemorySize,
                             TILE_BYTES);
        attr_set = true;
    }

    dim3 grid((PP + TILE - 1) / TILE, BB);               // 3125 x 2
    main_kernel<<<grid, NTHR, TILE_BYTES>>>(logits, masks, pad, out);

    remap_kernel<<<(BB * PP / 4 + 255) / 256, 256>>>(out);
}